// round 5
// baseline (speedup 1.0000x reference)
#include <cuda_runtime.h>
#include <cuda_bf16.h>
#include <cstdint>
#include <stdint.h>
#include <math.h>

#define BATCH 4
#define SEQ   2048
#define DM    1024
#define NH    16
#define HD    64
#define MTOT  (BATCH*SEQ)   // 8192

typedef unsigned int u32;

// Scratch (allocation-free rule: __device__ globals)
__device__ float g_Q [MTOT*DM];
__device__ float g_K [MTOT*DM];
__device__ float g_V [MTOT*DM];
__device__ float g_AO[MTOT*DM];
__device__ float g_X [MTOT*DM];
__device__ float g_Wq[DM*DM];
__device__ float g_Wk[DM*DM];
__device__ float g_Wv[DM*DM];
__device__ float g_Wo[DM*DM];

// ---------------------------------------------------------------------------
// helpers
// ---------------------------------------------------------------------------
__device__ __forceinline__ u32 f2tf(float f) {
    u32 u;
    asm("cvt.rna.tf32.f32 %0, %1;" : "=r"(u) : "f"(f));
    return u;
}

__device__ __forceinline__ void mma_tf32(float c[4], const u32 a[4],
                                         const u32 b[2]) {
    asm volatile(
        "mma.sync.aligned.m16n8k8.row.col.f32.tf32.tf32.f32 "
        "{%0,%1,%2,%3}, {%4,%5,%6,%7}, {%8,%9}, {%0,%1,%2,%3};"
        : "+f"(c[0]), "+f"(c[1]), "+f"(c[2]), "+f"(c[3])
        : "r"(a[0]), "r"(a[1]), "r"(a[2]), "r"(a[3]),
          "r"(b[0]), "r"(b[1]));
}

__device__ __forceinline__ u32 s2u(const void* p) {
    return (u32)__cvta_generic_to_shared(p);
}

#define CP16(dst, src) \
    asm volatile("cp.async.cg.shared.global [%0], [%1], 16;" :: "r"(dst), "l"(src) : "memory")
#define CP_COMMIT() asm volatile("cp.async.commit_group;" ::: "memory")
#define CP_WAIT0()  asm volatile("cp.async.wait_group 0;" ::: "memory")
#define CP_WAIT1()  asm volatile("cp.async.wait_group 1;" ::: "memory")

// ---------------------------------------------------------------------------
// Prep: round fp32 arrays to tf32 bits (round-to-nearest) once.
// ---------------------------------------------------------------------------
__global__ void round_tf(const float4* __restrict__ s, uint4* __restrict__ d,
                         int n4)
{
    for (int i = blockIdx.x * blockDim.x + threadIdx.x; i < n4;
         i += gridDim.x * blockDim.x) {
        float4 v = s[i];
        d[i] = make_uint4(f2tf(v.x), f2tf(v.y), f2tf(v.z), f2tf(v.w));
    }
}

// ---------------------------------------------------------------------------
// GEMM: C = A[M,1024] @ W[1024,1024]^T  (einsum 'md,nd->mn'), mma.sync tf32.
// Inputs pre-rounded to tf32 bits. 128x128x32 tile, 3-stage cp.async pipeline,
// 256 threads (8 warps, 4m x 2n), warp tile 32x64, 2 CTAs/SM.
// MODE 0: plain fp32 out.  MODE 1: Q (scale+RoPE+round+scatter).
// MODE 2: V (round+scatter).  MODE 3: K (RoPE+round+scatter).
// smem per stage: A[128][36] + B[128][36] u32 = 36864 B; 3 stages = 110592 B.
// ---------------------------------------------------------------------------
#define GS      36
#define STAGE_B 36864
#define G_SMEM  (3*STAGE_B)

template<int MODE>
__device__ __forceinline__ void g_issue(const float* A, const float* W,
                                        u32 sbase, int t, int m0, int n0,
                                        int tid)
{
    const int k0 = t * 32;
    const u32 st = sbase + (t % 3) * STAGE_B;
    const int ra = tid >> 1;
    const int c0 = (tid & 1) * 16;
    #pragma unroll
    for (int i = 0; i < 4; i++) {
        const int col = c0 + i * 4;
        CP16(st + ra * (GS*4) + col * 4,
             A + (size_t)(m0 + ra) * DM + k0 + col);
        CP16(st + 128 * (GS*4) + ra * (GS*4) + col * 4,
             W + (size_t)(n0 + ra) * DM + k0 + col);
    }
}

template<int MODE>
__global__ void __launch_bounds__(256, 2) gemm_k(
    const float* __restrict__ A, const float* __restrict__ W,
    float* __restrict__ C)
{
    extern __shared__ __align__(16) char smx[];
    const int tid  = threadIdx.x;
    const int lane = tid & 31;
    const int wid  = tid >> 5;
    const int g    = lane >> 2;
    const int tg   = lane & 3;
    const int wm   = (wid >> 1) * 32;
    const int wn   = (wid & 1) * 64;
    const int m0   = blockIdx.y * 128;
    const int n0   = blockIdx.x * 128;
    const u32 sbase = s2u(smx);

    float acc[2][8][4];
    #pragma unroll
    for (int mt = 0; mt < 2; mt++)
        #pragma unroll
        for (int nt = 0; nt < 8; nt++)
            #pragma unroll
            for (int r = 0; r < 4; r++) acc[mt][nt][r] = 0.0f;

    g_issue<MODE>(A, W, sbase, 0, m0, n0, tid); CP_COMMIT();
    g_issue<MODE>(A, W, sbase, 1, m0, n0, tid); CP_COMMIT();

    for (int t = 0; t < 32; t++) {
        CP_WAIT1();          // group t done; t+1 still in flight
        __syncthreads();     // data visible + prev compute done with buf (t+2)%3
        if (t + 2 < 32) g_issue<MODE>(A, W, sbase, t + 2, m0, n0, tid);
        CP_COMMIT();

        const u32* pA = (const u32*)(smx + (t % 3) * STAGE_B);
        const u32* pB = pA + 128 * GS;

        #pragma unroll
        for (int kk = 0; kk < 32; kk += 8) {
            u32 af[2][4], bf[8][2];
            #pragma unroll
            for (int mt = 0; mt < 2; mt++) {
                int r = wm + mt * 16 + g;
                af[mt][0] = pA[r * GS + kk + tg];
                af[mt][1] = pA[(r + 8) * GS + kk + tg];
                af[mt][2] = pA[r * GS + kk + tg + 4];
                af[mt][3] = pA[(r + 8) * GS + kk + tg + 4];
            }
            #pragma unroll
            for (int nt = 0; nt < 8; nt++) {
                int c = wn + nt * 8 + g;
                bf[nt][0] = pB[c * GS + kk + tg];
                bf[nt][1] = pB[c * GS + kk + tg + 4];
            }
            #pragma unroll
            for (int mt = 0; mt < 2; mt++)
                #pragma unroll
                for (int nt = 0; nt < 8; nt++)
                    mma_tf32(acc[mt][nt], af[mt], bf[nt]);
        }
    }

    // Epilogue
    #pragma unroll
    for (int mt = 0; mt < 2; mt++) {
        #pragma unroll
        for (int nt = 0; nt < 8; nt++) {
            const int gn    = n0 + wn + nt * 8 + 2 * tg;  // even column
            const int rbase = m0 + wm + mt * 16 + g;
            if (MODE == 0) {
                *(float2*)(C + (size_t)rbase * DM + gn) =
                    make_float2(acc[mt][nt][0], acc[mt][nt][1]);
                *(float2*)(C + (size_t)(rbase + 8) * DM + gn) =
                    make_float2(acc[mt][nt][2], acc[mt][nt][3]);
            } else {
                const int h  = gn >> 6;
                const int d0 = gn & 63;
                float invf = 0.0f;
                if (MODE == 1 || MODE == 3)
                    invf = exp2f((float)d0 * (-13.287712379549449f / 64.0f));
                #pragma unroll
                for (int half = 0; half < 2; half++) {
                    int m = rbase + half * 8;
                    int b = m >> 11;
                    int s = m & (SEQ - 1);
                    float e = acc[mt][nt][half * 2];
                    float o = acc[mt][nt][half * 2 + 1];
                    if (MODE == 1) { e *= 0.125f; o *= 0.125f; }
                    float r1, r2;
                    if (MODE == 1 || MODE == 3) {
                        float sn, cs;
                        sincosf((float)s * invf, &sn, &cs);
                        r1 = e * cs - o * sn;
                        r2 = e * sn + o * cs;
                    } else { r1 = e; r2 = o; }
                    size_t idx = (((size_t)(b * NH + h)) * SEQ + s) * HD + d0;
                    *(float2*)(C + idx) =
                        make_float2(__uint_as_float(f2tf(r1)),
                                    __uint_as_float(f2tf(r2)));
                }
            }
        }
    }
}

// ---------------------------------------------------------------------------
// Flash attention (causal), mma.sync tf32. Q/K/V pre-rounded tf32 bits,
// Q pre-scaled by 1/8. 256 threads / 8 warps, 128 q rows, K/V tiles of 64,
// 2-buffer cp.async pipeline (prefetch t+1 under compute of t).
// Q fragments cached in registers.
// ---------------------------------------------------------------------------
#define ATP 68
#define ATTN_SMEM ((128 + 2*64 + 2*64 + 128) * ATP * 4)   // 139264 B

__device__ __forceinline__ void a_issue(const float* Kb, const float* Vb,
                                        u32 skb, u32 svb, int t, int tid)
{
    const int n0 = t * 64;
    const int pr = tid >> 2;
    const u32 soff = (t & 1) * 64 * ATP * 4;
    #pragma unroll
    for (int i = 0; i < 4; i++) {
        const int cc = ((tid & 3) + i * 4) * 4;   // f32 col
        CP16(skb + soff + pr * (ATP*4) + cc * 4,
             Kb + (size_t)(n0 + pr) * HD + cc);
        CP16(svb + soff + pr * (ATP*4) + cc * 4,
             Vb + (size_t)(n0 + pr) * HD + cc);
    }
}

__global__ void __launch_bounds__(256, 1) attn_k(
    const float* __restrict__ Q, const float* __restrict__ K,
    const float* __restrict__ V, float* __restrict__ O)
{
    extern __shared__ u32 smu[];
    u32* sQ  = smu;                        // [128][ATP]
    u32* sKb = sQ  + 128 * ATP;            // 2 x [64][ATP]
    u32* sVb = sKb + 2 * 64 * ATP;         // 2 x [64][ATP]
    u32* sP  = sVb + 2 * 64 * ATP;         // [128][ATP]

    const int tid  = threadIdx.x;
    const int lane = tid & 31;
    const int wid  = tid >> 5;
    const int g    = lane >> 2;
    const int tg   = lane & 3;
    const int qw   = wid * 16;
    const int bh   = blockIdx.y;
    const int m0   = blockIdx.x * 128;

    const float* Qb = Q + ((size_t)bh * SEQ + m0) * HD;
    const float* Kb = K + (size_t)bh * SEQ * HD;
    const float* Vb = V + (size_t)bh * SEQ * HD;

    const u32 skb = s2u(sKb);
    const u32 svb = s2u(sVb);
    const int ntiles = 2 * blockIdx.x + 2;

    // Load Q tile (raw pre-rounded/pre-scaled bits) into smem
    {
        const int lr  = tid >> 4;
        const int lc4 = (tid & 15) << 2;
        #pragma unroll
        for (int rr = 0; rr < 128; rr += 16) {
            uint4 v = *(const uint4*)(Qb + (size_t)(lr + rr) * HD + lc4);
            *(uint4*)&sQ[(lr + rr) * ATP + lc4] = v;
        }
    }

    a_issue(Kb, Vb, skb, svb, 0, tid); CP_COMMIT();

    float oacc[8][4];
    #pragma unroll
    for (int nt = 0; nt < 8; nt++)
        #pragma unroll
        for (int r = 0; r < 4; r++) oacc[nt][r] = 0.0f;
    float m_0 = -1e30f, m_1 = -1e30f, l0 = 0.0f, l1 = 0.0f;

    const int q0g = m0 + qw + g;
    const int q1g = q0g + 8;

    u32 qf[32];   // Q fragments, loaded once

    for (int t = 0; t < ntiles; t++) {
        CP_WAIT0();          // tile t loaded
        __syncthreads();     // visible to all; prev compute done with buf t&1's partner

        if (t == 0) {
            #pragma unroll
            for (int kk = 0; kk < 8; kk++) {
                qf[kk*4+0] = sQ[(qw + g    ) * ATP + kk * 8 + tg];
                qf[kk*4+1] = sQ[(qw + g + 8) * ATP + kk * 8 + tg];
                qf[kk*4+2] = sQ[(qw + g    ) * ATP + kk * 8 + tg + 4];
                qf[kk*4+3] = sQ[(qw + g + 8) * ATP + kk * 8 + tg + 4];
            }
        }

        if (t + 1 < ntiles) a_issue(Kb, Vb, skb, svb, t + 1, tid);
        CP_COMMIT();

        const u32* sK = sKb + (t & 1) * 64 * ATP;
        const u32* sV = sVb + (t & 1) * 64 * ATP;
        const int n0 = t * 64;

        // S = Q @ K^T  (pre-scaled)
        float sf[8][4];
        #pragma unroll
        for (int nt = 0; nt < 8; nt++)
            #pragma unroll
            for (int r = 0; r < 4; r++) sf[nt][r] = 0.0f;

        #pragma unroll
        for (int kk = 0; kk < 8; kk++) {
            #pragma unroll
            for (int nt = 0; nt < 8; nt++) {
                u32 bf[2];
                bf[0] = sK[(nt * 8 + g) * ATP + kk * 8 + tg];
                bf[1] = sK[(nt * 8 + g) * ATP + kk * 8 + tg + 4];
                mma_tf32(sf[nt], &qf[kk*4], bf);
            }
        }

        // Causal mask (only tiles overlapping the diagonal)
        if (t >= 2 * (int)blockIdx.x) {
            #pragma unroll
            for (int nt = 0; nt < 8; nt++) {
                int jg = n0 + nt * 8 + 2 * tg;
                if (jg     > q0g) sf[nt][0] = -1e30f;
                if (jg + 1 > q0g) sf[nt][1] = -1e30f;
                if (jg     > q1g) sf[nt][2] = -1e30f;
                if (jg + 1 > q1g) sf[nt][3] = -1e30f;
            }
        }

        // Online softmax
        float mx0 = -1e30f, mx1 = -1e30f;
        #pragma unroll
        for (int nt = 0; nt < 8; nt++) {
            mx0 = fmaxf(mx0, fmaxf(sf[nt][0], sf[nt][1]));
            mx1 = fmaxf(mx1, fmaxf(sf[nt][2], sf[nt][3]));
        }
        mx0 = fmaxf(mx0, __shfl_xor_sync(0xffffffffu, mx0, 1));
        mx0 = fmaxf(mx0, __shfl_xor_sync(0xffffffffu, mx0, 2));
        mx1 = fmaxf(mx1, __shfl_xor_sync(0xffffffffu, mx1, 1));
        mx1 = fmaxf(mx1, __shfl_xor_sync(0xffffffffu, mx1, 2));

        float mn0 = fmaxf(m_0, mx0);
        float mn1 = fmaxf(m_1, mx1);
        float c0 = __expf(m_0 - mn0);
        float c1 = __expf(m_1 - mn1);
        m_0 = mn0; m_1 = mn1;

        float s0 = 0.0f, s1 = 0.0f;
        #pragma unroll
        for (int nt = 0; nt < 8; nt++) {
            float p00 = __expf(sf[nt][0] - mn0);
            float p01 = __expf(sf[nt][1] - mn0);
            float p10 = __expf(sf[nt][2] - mn1);
            float p11 = __expf(sf[nt][3] - mn1);
            s0 += p00 + p01;
            s1 += p10 + p11;
            int cc = nt * 8 + 2 * tg;
            sP[(qw + g    ) * ATP + cc    ] = f2tf(p00);
            sP[(qw + g    ) * ATP + cc + 1] = f2tf(p01);
            sP[(qw + g + 8) * ATP + cc    ] = f2tf(p10);
            sP[(qw + g + 8) * ATP + cc + 1] = f2tf(p11);
        }
        s0 += __shfl_xor_sync(0xffffffffu, s0, 1);
        s0 += __shfl_xor_sync(0xffffffffu, s0, 2);
        s1 += __shfl_xor_sync(0xffffffffu, s1, 1);
        s1 += __shfl_xor_sync(0xffffffffu, s1, 2);
        l0 = l0 * c0 + s0;
        l1 = l1 * c1 + s1;

        #pragma unroll
        for (int nt = 0; nt < 8; nt++) {
            oacc[nt][0] *= c0; oacc[nt][1] *= c0;
            oacc[nt][2] *= c1; oacc[nt][3] *= c1;
        }
        __syncwarp();   // sP rows are warp-private

        // O += P @ V
        #pragma unroll
        for (int kk = 0; kk < 8; kk++) {
            u32 af[4];
            af[0] = sP[(qw + g    ) * ATP + kk * 8 + tg];
            af[1] = sP[(qw + g + 8) * ATP + kk * 8 + tg];
            af[2] = sP[(qw + g    ) * ATP + kk * 8 + tg + 4];
            af[3] = sP[(qw + g + 8) * ATP + kk * 8 + tg + 4];
            #pragma unroll
            for (int nt = 0; nt < 8; nt++) {
                u32 bf[2];
                bf[0] = sV[(kk * 8 + tg    ) * ATP + nt * 8 + g];
                bf[1] = sV[(kk * 8 + tg + 4) * ATP + nt * 8 + g];
                mma_tf32(oacc[nt], af, bf);
            }
        }
    }

    // Normalize + write out as [B, S, DM], tf32-rounded for the O-proj GEMM
    const int b = bh >> 4;
    const int h = bh & 15;
    const float inv0 = 1.0f / l0;
    const float inv1 = 1.0f / l1;
    #pragma unroll
    for (int nt = 0; nt < 8; nt++) {
        int col = h * HD + nt * 8 + 2 * tg;
        *(float2*)(O + ((size_t)(b * SEQ + q0g)) * DM + col) =
            make_float2(__uint_as_float(f2tf(oacc[nt][0] * inv0)),
                        __uint_as_float(f2tf(oacc[nt][1] * inv0)));
        *(float2*)(O + ((size_t)(b * SEQ + q1g)) * DM + col) =
            make_float2(__uint_as_float(f2tf(oacc[nt][2] * inv1)),
                        __uint_as_float(f2tf(oacc[nt][3] * inv1)));
    }
}

// ---------------------------------------------------------------------------
extern "C" void kernel_launch(void* const* d_in, const int* in_sizes, int n_in,
                              void* d_out, int out_size)
{
    const float* qw = (const float*)d_in[0];
    const float* kw = (const float*)d_in[1];
    const float* vw = (const float*)d_in[2];
    const float* ow = (const float*)d_in[3];
    const float* x  = (const float*)d_in[4];
    float* out = (float*)d_out;

    float *Qp, *Kp, *Vp, *AOp, *Xp, *Wqp, *Wkp, *Wvp, *Wop;
    cudaGetSymbolAddress((void**)&Qp,  g_Q);
    cudaGetSymbolAddress((void**)&Kp,  g_K);
    cudaGetSymbolAddress((void**)&Vp,  g_V);
    cudaGetSymbolAddress((void**)&AOp, g_AO);
    cudaGetSymbolAddress((void**)&Xp,  g_X);
    cudaGetSymbolAddress((void**)&Wqp, g_Wq);
    cudaGetSymbolAddress((void**)&Wkp, g_Wk);
    cudaGetSymbolAddress((void**)&Wvp, g_Wv);
    cudaGetSymbolAddress((void**)&Wop, g_Wo);

    cudaFuncSetAttribute(gemm_k<0>, cudaFuncAttributeMaxDynamicSharedMemorySize, G_SMEM);
    cudaFuncSetAttribute(gemm_k<1>, cudaFuncAttributeMaxDynamicSharedMemorySize, G_SMEM);
    cudaFuncSetAttribute(gemm_k<2>, cudaFuncAttributeMaxDynamicSharedMemorySize, G_SMEM);
    cudaFuncSetAttribute(gemm_k<3>, cudaFuncAttributeMaxDynamicSharedMemorySize, G_SMEM);
    cudaFuncSetAttribute(attn_k, cudaFuncAttributeMaxDynamicSharedMemorySize, ATTN_SMEM);

    // Pre-round inputs to tf32 (round-to-nearest) once
    round_tf<<<2048, 256>>>((const float4*)x,  (uint4*)Xp,  MTOT*DM/4);
    round_tf<<<1024, 256>>>((const float4*)qw, (uint4*)Wqp, DM*DM/4);
    round_tf<<<1024, 256>>>((const float4*)kw, (uint4*)Wkp, DM*DM/4);
    round_tf<<<1024, 256>>>((const float4*)vw, (uint4*)Wvp, DM*DM/4);
    round_tf<<<1024, 256>>>((const float4*)ow, (uint4*)Wop, DM*DM/4);

    dim3 gg(DM/128, MTOT/128);   // (8, 64)
    gemm_k<1><<<gg, 256, G_SMEM>>>(Xp, Wqp, Qp);   // Q proj + scale + RoPE
    gemm_k<3><<<gg, 256, G_SMEM>>>(Xp, Wkp, Kp);   // K proj + RoPE
    gemm_k<2><<<gg, 256, G_SMEM>>>(Xp, Wvp, Vp);   // V proj

    attn_k<<<dim3(SEQ/128, BATCH*NH), 256, ATTN_SMEM>>>(Qp, Kp, Vp, AOp);

    gemm_k<0><<<gg, 256, G_SMEM>>>(AOp, Wop, out); // O proj -> d_out
}